// round 10
// baseline (speedup 1.0000x reference)
#include <cuda_runtime.h>
#include <cuda_bf16.h>
#include <cstdint>

#define NB 4
#define NC 128
#define NCI 64
#define NN 4096

// Scratch (device globals — no allocation allowed)
__device__ __align__(16) __nv_bfloat16 d_theta[NB * NN * NCI]; // [b][n][ci] (Q)
__device__ __align__(16) __nv_bfloat16 d_phi[NB * NN * NCI];   // [b][n][ci] (K)
__device__ __align__(16) __nv_bfloat16 d_g[NB * NN * NCI];     // [b][n][ci] (V)
__device__ __align__(16) float d_y[NB * NCI * NN];             // [b][ci][n] fp32

// FFMA-only exp (MUFU would bottleneck for 67M exps).
__device__ __forceinline__ float fast_exp(float x) {
    x = fmaxf(x, -60.0f);
    float t = x * 1.4426950408889634f;
    float r = t + 12582912.0f;
    int   i = __float_as_int(r) - 0x4B400000;
    float f = t - (r - 12582912.0f);
    float p = 1.33336e-3f;
    p = fmaf(p, f, 9.61813e-3f);
    p = fmaf(p, f, 5.550411e-2f);
    p = fmaf(p, f, 2.4022651e-1f);
    p = fmaf(p, f, 6.9314718e-1f);
    p = fmaf(p, f, 1.0f);
    return __int_as_float(__float_as_int(p) + (i << 23));
}

__device__ __forceinline__ uint32_t pack_bf16(float lo, float hi) {
    __nv_bfloat162 h = __floats2bfloat162_rn(lo, hi);
    return *(uint32_t*)&h;
}

__device__ __forceinline__ uint32_t smem_u32(const void* p) {
    return (uint32_t)__cvta_generic_to_shared(p);
}

__device__ __forceinline__ void mma_bf16(float c[4], const uint32_t a[4],
                                         uint32_t b0, uint32_t b1) {
    asm volatile(
        "mma.sync.aligned.m16n8k16.row.col.f32.bf16.bf16.f32 "
        "{%0,%1,%2,%3}, {%4,%5,%6,%7}, {%8,%9}, {%0,%1,%2,%3};\n"
        : "+f"(c[0]), "+f"(c[1]), "+f"(c[2]), "+f"(c[3])
        : "r"(a[0]), "r"(a[1]), "r"(a[2]), "r"(a[3]), "r"(b0), "r"(b1));
}

__device__ __forceinline__ void ldsm_x4(uint32_t r[4], uint32_t addr) {
    asm volatile("ldmatrix.sync.aligned.m8n8.x4.shared.b16 {%0,%1,%2,%3}, [%4];"
                 : "=r"(r[0]), "=r"(r[1]), "=r"(r[2]), "=r"(r[3]) : "r"(addr));
}
__device__ __forceinline__ void ldsm_x4_t(uint32_t r[4], uint32_t addr) {
    asm volatile("ldmatrix.sync.aligned.m8n8.x4.trans.shared.b16 {%0,%1,%2,%3}, [%4];"
                 : "=r"(r[0]), "=r"(r[1]), "=r"(r[2]), "=r"(r[3]) : "r"(addr));
}

// cp.async one 64x64-bf16 tile (64 rows x 128B) into swizzled smem
__device__ __forceinline__ void load_tile_async(uint32_t dst,
                                                const __nv_bfloat16* src, int t) {
#pragma unroll
    for (int e = t; e < 512; e += 128) {
        int row = e >> 3, chunk = e & 7;
        uint32_t d = dst + row * 128 + ((chunk ^ (row & 7)) << 4);
        const void* s = (const uint8_t*)(src + (size_t)row * NCI) + chunk * 16;
        asm volatile("cp.async.cg.shared.global [%0], [%1], 16;\n" :: "r"(d), "l"(s));
    }
}

// ---------------------------------------------------------------------------
// Projections: out[n][ci] = sum_c w[ci][c] * x[c][n] + b[ci]   (bf16 output)
// z=0: theta(x1); z=1: phi(x0); z=2: g(x0).
// ---------------------------------------------------------------------------
__global__ void __launch_bounds__(256) proj_kernel(
    const float* __restrict__ x0, const float* __restrict__ x1,
    const float* __restrict__ theta_w, const float* __restrict__ theta_b,
    const float* __restrict__ phi_w,   const float* __restrict__ phi_b,
    const float* __restrict__ g_w,     const float* __restrict__ g_b)
{
    __shared__ __align__(16) float ws[64 * 64];   // [c_local][ci]
    __shared__ __align__(16) float xs[64 * 128];  // [c_local][p]

    int b = blockIdx.y;
    int n0 = blockIdx.x * 128;
    int which = blockIdx.z;
    const float* w    = (which == 0) ? theta_w : ((which == 1) ? phi_w : g_w);
    const float* bias = (which == 0) ? theta_b : ((which == 1) ? phi_b : g_b);
    const float* src  = (which == 0) ? x1 : x0;

    int t = threadIdx.x;
    int tx = t & 15, ty = t >> 4;
    int ci0 = ty * 4, p0 = tx * 4;

    float acc[4][8];
#pragma unroll
    for (int i = 0; i < 4; i++)
#pragma unroll
        for (int j = 0; j < 8; j++) acc[i][j] = 0.0f;

    const float* xb = src + (size_t)b * NC * NN + n0;

    for (int h = 0; h < 2; h++) {
        if (h) __syncthreads();
        for (int e = t; e < 64 * 64; e += 256) {
            int ci = e >> 6, cl = e & 63;
            ws[cl * 64 + ci] = w[ci * NC + h * 64 + cl];
        }
        for (int e = t; e < 64 * 128; e += 256) {
            int cl = e >> 7, p = e & 127;
            xs[cl * 128 + p] = xb[(size_t)(h * 64 + cl) * NN + p];
        }
        __syncthreads();
#pragma unroll 4
        for (int cl = 0; cl < 64; cl++) {
            float4 wv = *(const float4*)&ws[cl * 64 + ci0];
            float4 xa = *(const float4*)&xs[cl * 128 + p0];
            float4 xc = *(const float4*)&xs[cl * 128 + p0 + 64];
            float wr[4] = {wv.x, wv.y, wv.z, wv.w};
            float xr[8] = {xa.x, xa.y, xa.z, xa.w, xc.x, xc.y, xc.z, xc.w};
#pragma unroll
            for (int i = 0; i < 4; i++)
#pragma unroll
                for (int j = 0; j < 8; j++)
                    acc[i][j] = fmaf(wr[i], xr[j], acc[i][j]);
        }
    }

    __nv_bfloat16* out = ((which == 0) ? d_theta : ((which == 1) ? d_phi : d_g))
                         + (size_t)b * NN * NCI + (size_t)n0 * NCI;
    float b0v = bias[ci0], b1v = bias[ci0 + 1], b2v = bias[ci0 + 2], b3v = bias[ci0 + 3];
#pragma unroll
    for (int jj = 0; jj < 8; jj++) {
        int p = (jj < 4) ? (p0 + jj) : (p0 + 60 + jj);
        uint2 v;
        v.x = pack_bf16(acc[0][jj] + b0v, acc[1][jj] + b1v);
        v.y = pack_bf16(acc[2][jj] + b2v, acc[3][jj] + b3v);
        *(uint2*)&out[(size_t)p * NCI + ci0] = v;
    }
}

// ---------------------------------------------------------------------------
// Flash attention, bf16 m16n8k16 mma. One CTA = 64 queries, 4 warps, 128 thr.
// Q a-frags register-resident (via ldmatrix from staged smem).
// K tile [kidx][d], V tile [kidx][d] in smem, 128B rows, chunk^(row&7) swizzle.
// S B-frags: ldmatrix.x4; V B-frags: ldmatrix.x4.trans.
// P A-frags = packed S C-frags (no shuffles). cp.async double buffering.
// ---------------------------------------------------------------------------
__global__ void __launch_bounds__(128) attn_kernel()
{
    __shared__ __align__(16) uint8_t Qsm[64 * 128];
    __shared__ __align__(16) uint8_t Ksm[2][64 * 128];
    __shared__ __align__(16) uint8_t Vsm[2][64 * 128];

    int b = blockIdx.y;
    int qb = blockIdx.x * 64;
    int t = threadIdx.x;
    int w = t >> 5, lane = t & 31;
    int g = lane >> 2, j = lane & 3;
    int sel = lane >> 3, l7 = lane & 7;

    const __nv_bfloat16* Qg = d_theta + (size_t)b * NN * NCI + (size_t)qb * NCI;
    const __nv_bfloat16* Kg = d_phi   + (size_t)b * NN * NCI;
    const __nv_bfloat16* Vg = d_g     + (size_t)b * NN * NCI;

    uint32_t smQ  = smem_u32(Qsm);
    uint32_t smK0 = smem_u32(Ksm[0]), smK1 = smem_u32(Ksm[1]);
    uint32_t smV0 = smem_u32(Vsm[0]), smV1 = smem_u32(Vsm[1]);

    // prologue: start tile-0 K/V loads
    load_tile_async(smK0, Kg, t);
    load_tile_async(smV0, Vg, t);
    asm volatile("cp.async.commit_group;\n");

    // stage Q tile (overlaps with the cp.async above)
#pragma unroll
    for (int e = t; e < 512; e += 128) {
        int row = e >> 3, chunk = e & 7;
        uint4 v = *(const uint4*)((const uint8_t*)(Qg + (size_t)row * NCI) + chunk * 16);
        *(uint4*)&Qsm[row * 128 + ((chunk ^ (row & 7)) << 4)] = v;
    }
    __syncthreads();

    // Q a-frags for 4 k-steps (d = 16*ks .. 16*ks+15)
    uint32_t qa[4][4];
#pragma unroll
    for (int ks = 0; ks < 4; ks++) {
        int row = w * 16 + ((sel & 1) << 3) + l7;
        int chunk = 2 * ks + (sel >> 1);
        ldsm_x4(qa[ks], smQ + row * 128 + ((chunk ^ (row & 7)) << 4));
    }

    float o[8][4];
#pragma unroll
    for (int nt = 0; nt < 8; nt++)
#pragma unroll
        for (int i = 0; i < 4; i++) o[nt][i] = 0.0f;
    float m0 = -1e30f, m1 = -1e30f, l0 = 0.0f, l1 = 0.0f;

    for (int it = 0; it < NN / 64; it++) {
        uint32_t smKb = (it & 1) ? smK1 : smK0;
        uint32_t smVb = (it & 1) ? smV1 : smV0;
        if (it + 1 < NN / 64) {
            uint32_t smKn = (it & 1) ? smK0 : smK1;
            uint32_t smVn = (it & 1) ? smV0 : smV1;
            load_tile_async(smKn, Kg + (size_t)(it + 1) * 64 * NCI, t);
            load_tile_async(smVn, Vg + (size_t)(it + 1) * 64 * NCI, t);
            asm volatile("cp.async.commit_group;\n");
            asm volatile("cp.async.wait_group 1;\n");
        } else {
            asm volatile("cp.async.wait_group 0;\n");
        }
        __syncthreads();

        // ---- S = Q K^T ----
        float s[8][4];
#pragma unroll
        for (int nt = 0; nt < 8; nt++)
#pragma unroll
            for (int i = 0; i < 4; i++) s[nt][i] = 0.0f;

#pragma unroll
        for (int ks = 0; ks < 4; ks++) {
#pragma unroll
            for (int ntp = 0; ntp < 4; ntp++) {
                int row = ntp * 16 + ((sel >> 1) << 3) + l7;
                int chunk = 2 * ks + (sel & 1);
                uint32_t r[4];
                ldsm_x4(r, smKb + row * 128 + ((chunk ^ (row & 7)) << 4));
                mma_bf16(s[2 * ntp], qa[ks], r[0], r[1]);
                mma_bf16(s[2 * ntp + 1], qa[ks], r[2], r[3]);
            }
        }

        // ---- online softmax: rows g (regs 0,1) and g+8 (regs 2,3) ----
        float t0 = -1e30f, t1 = -1e30f;
#pragma unroll
        for (int nt = 0; nt < 8; nt++) {
            t0 = fmaxf(t0, fmaxf(s[nt][0], s[nt][1]));
            t1 = fmaxf(t1, fmaxf(s[nt][2], s[nt][3]));
        }
        t0 = fmaxf(t0, __shfl_xor_sync(0xffffffffu, t0, 1));
        t0 = fmaxf(t0, __shfl_xor_sync(0xffffffffu, t0, 2));
        t1 = fmaxf(t1, __shfl_xor_sync(0xffffffffu, t1, 1));
        t1 = fmaxf(t1, __shfl_xor_sync(0xffffffffu, t1, 2));
        float nm0 = fmaxf(m0, t0), nm1 = fmaxf(m1, t1);
        float sc0 = fast_exp(m0 - nm0), sc1 = fast_exp(m1 - nm1);
        float rs0 = 0.0f, rs1 = 0.0f;
#pragma unroll
        for (int nt = 0; nt < 8; nt++) {
            s[nt][0] = fast_exp(s[nt][0] - nm0);
            s[nt][1] = fast_exp(s[nt][1] - nm0);
            s[nt][2] = fast_exp(s[nt][2] - nm1);
            s[nt][3] = fast_exp(s[nt][3] - nm1);
            rs0 += s[nt][0] + s[nt][1];
            rs1 += s[nt][2] + s[nt][3];
        }
        rs0 += __shfl_xor_sync(0xffffffffu, rs0, 1);
        rs0 += __shfl_xor_sync(0xffffffffu, rs0, 2);
        rs1 += __shfl_xor_sync(0xffffffffu, rs1, 1);
        rs1 += __shfl_xor_sync(0xffffffffu, rs1, 2);
        l0 = fmaf(l0, sc0, rs0);
        l1 = fmaf(l1, sc1, rs1);
        m0 = nm0; m1 = nm1;
#pragma unroll
        for (int nt = 0; nt < 8; nt++) {
            o[nt][0] *= sc0; o[nt][1] *= sc0;
            o[nt][2] *= sc1; o[nt][3] *= sc1;
        }

        // ---- O += P V : P A-frags = packed C-frags ----
#pragma unroll
        for (int ks = 0; ks < 4; ks++) {
            uint32_t ap[4];
            ap[0] = pack_bf16(s[2 * ks][0], s[2 * ks][1]);
            ap[1] = pack_bf16(s[2 * ks][2], s[2 * ks][3]);
            ap[2] = pack_bf16(s[2 * ks + 1][0], s[2 * ks + 1][1]);
            ap[3] = pack_bf16(s[2 * ks + 1][2], s[2 * ks + 1][3]);
#pragma unroll
            for (int ntp = 0; ntp < 4; ntp++) {
                int row = 16 * ks + ((sel & 1) << 3) + l7;
                int chunk = 2 * ntp + (sel >> 1);
                uint32_t r[4];
                ldsm_x4_t(r, smVb + row * 128 + ((chunk ^ (row & 7)) << 4));
                mma_bf16(o[2 * ntp], ap, r[0], r[1]);
                mma_bf16(o[2 * ntp + 1], ap, r[2], r[3]);
            }
        }
        __syncthreads();
    }

    // ---- epilogue: y[b][d][n] = O / l   (fp32, [ci][n]) ----
    float inv0 = 1.0f / l0, inv1 = 1.0f / l1;
    float* yo = d_y + (size_t)b * NCI * NN;
    int q0 = qb + w * 16;
    int qg0 = q0 + g, qg1 = q0 + g + 8;
#pragma unroll
    for (int nt = 0; nt < 8; nt++) {
        int d0 = nt * 8 + 2 * j;
        yo[(size_t)d0 * NN + qg0]       = o[nt][0] * inv0;
        yo[(size_t)(d0 + 1) * NN + qg0] = o[nt][1] * inv0;
        yo[(size_t)d0 * NN + qg1]       = o[nt][2] * inv1;
        yo[(size_t)(d0 + 1) * NN + qg1] = o[nt][3] * inv1;
    }
}

// ---------------------------------------------------------------------------
// out[b][co][n] = sum_ci Ww[co][ci] * y[b][ci][n] + Wb[co] + x0[b][co][n]
// ---------------------------------------------------------------------------
__global__ void __launch_bounds__(256) out_kernel(
    const float* __restrict__ x0, const float* __restrict__ Ww,
    const float* __restrict__ Wb, float* __restrict__ out)
{
    __shared__ __align__(16) float ws[32 * 128]; // [ci_local][co]
    __shared__ __align__(16) float ys[32 * 128]; // [ci_local][p]

    int b = blockIdx.y;
    int n0 = blockIdx.x * 128;
    int t = threadIdx.x;
    int tx = t & 15, ty = t >> 4;
    int co0 = ty * 4, p0 = tx * 4;

    float acc[8][8];
#pragma unroll
    for (int i = 0; i < 8; i++)
#pragma unroll
        for (int j = 0; j < 8; j++) acc[i][j] = 0.0f;

    const float* yg = d_y + (size_t)b * NCI * NN + n0;

    for (int h = 0; h < 2; h++) {
        if (h) __syncthreads();
        for (int e = t; e < 128 * 32; e += 256) {
            int co = e >> 5, cil = e & 31;
            ws[cil * 128 + co] = Ww[co * NCI + h * 32 + cil];
        }
        for (int e = t; e < 32 * 128; e += 256) {
            int cil = e >> 7, p = e & 127;
            ys[cil * 128 + p] = yg[(size_t)(h * 32 + cil) * NN + p];
        }
        __syncthreads();
#pragma unroll 4
        for (int cil = 0; cil < 32; cil++) {
            float4 wa = *(const float4*)&ws[cil * 128 + co0];
            float4 wc = *(const float4*)&ws[cil * 128 + co0 + 64];
            float4 ya = *(const float4*)&ys[cil * 128 + p0];
            float4 yc = *(const float4*)&ys[cil * 128 + p0 + 64];
            float wr[8] = {wa.x, wa.y, wa.z, wa.w, wc.x, wc.y, wc.z, wc.w};
            float yr[8] = {ya.x, ya.y, ya.z, ya.w, yc.x, yc.y, yc.z, yc.w};
#pragma unroll
            for (int i = 0; i < 8; i++)
#pragma unroll
                for (int j = 0; j < 8; j++)
                    acc[i][j] = fmaf(wr[i], yr[j], acc[i][j]);
        }
    }

    const float* xb = x0 + (size_t)b * NC * NN + n0;
    float* ob = out + (size_t)b * NC * NN + n0;
#pragma unroll
    for (int ih = 0; ih < 2; ih++)
#pragma unroll
        for (int i = 0; i < 4; i++) {
            int co = co0 + ih * 64 + i;
            float bv = Wb[co];
            int ai = ih * 4 + i;
#pragma unroll
            for (int jh = 0; jh < 2; jh++) {
                int p = p0 + jh * 64;
                int aj = jh * 4;
                float4 xv = *(const float4*)&xb[(size_t)co * NN + p];
                float4 r = make_float4(acc[ai][aj + 0] + bv + xv.x,
                                       acc[ai][aj + 1] + bv + xv.y,
                                       acc[ai][aj + 2] + bv + xv.z,
                                       acc[ai][aj + 3] + bv + xv.w);
                *(float4*)&ob[(size_t)co * NN + p] = r;
            }
        }
}

extern "C" void kernel_launch(void* const* d_in, const int* in_sizes, int n_in,
                              void* d_out, int out_size)
{
    const float* x0   = (const float*)d_in[0];
    const float* x1   = (const float*)d_in[1];
    const float* g_w  = (const float*)d_in[2];
    const float* g_b  = (const float*)d_in[3];
    const float* th_w = (const float*)d_in[4];
    const float* th_b = (const float*)d_in[5];
    const float* ph_w = (const float*)d_in[6];
    const float* ph_b = (const float*)d_in[7];
    const float* W_w  = (const float*)d_in[8];
    const float* W_b  = (const float*)d_in[9];
    float* out = (float*)d_out;

    proj_kernel<<<dim3(NN / 128, NB, 3), 256>>>(x0, x1, th_w, th_b, ph_w, ph_b, g_w, g_b);
    attn_kernel<<<dim3(NN / 64, NB), 128>>>();
    out_kernel<<<dim3(NN / 128, NB), 256>>>(x0, W_w, W_b, out);
}

// round 11
// speedup vs baseline: 1.0089x; 1.0089x over previous
#include <cuda_runtime.h>
#include <cuda_bf16.h>
#include <cstdint>

#define NB 4
#define NC 128
#define NCI 64
#define NN 4096

// Scratch (device globals — no allocation allowed)
__device__ __align__(16) __nv_bfloat16 d_theta[NB * NN * NCI]; // [b][n][ci] (Q)
__device__ __align__(16) __nv_bfloat16 d_phi[NB * NN * NCI];   // [b][n][ci] (K)
__device__ __align__(16) __nv_bfloat16 d_g[NB * NN * NCI];     // [b][n][ci] (V)
__device__ __align__(16) float d_y[NB * NCI * NN];             // [b][ci][n] fp32

// FFMA-only exp (MUFU would bottleneck for 67M exps).
__device__ __forceinline__ float fast_exp(float x) {
    x = fmaxf(x, -60.0f);
    float t = x * 1.4426950408889634f;
    float r = t + 12582912.0f;
    int   i = __float_as_int(r) - 0x4B400000;
    float f = t - (r - 12582912.0f);
    float p = 1.33336e-3f;
    p = fmaf(p, f, 9.61813e-3f);
    p = fmaf(p, f, 5.550411e-2f);
    p = fmaf(p, f, 2.4022651e-1f);
    p = fmaf(p, f, 6.9314718e-1f);
    p = fmaf(p, f, 1.0f);
    return __int_as_float(__float_as_int(p) + (i << 23));
}

__device__ __forceinline__ uint32_t pack_bf16(float lo, float hi) {
    __nv_bfloat162 h = __floats2bfloat162_rn(lo, hi);
    return *(uint32_t*)&h;
}

__device__ __forceinline__ uint32_t smem_u32(const void* p) {
    return (uint32_t)__cvta_generic_to_shared(p);
}

__device__ __forceinline__ void mma_bf16(float c[4], const uint32_t a[4],
                                         uint32_t b0, uint32_t b1) {
    asm volatile(
        "mma.sync.aligned.m16n8k16.row.col.f32.bf16.bf16.f32 "
        "{%0,%1,%2,%3}, {%4,%5,%6,%7}, {%8,%9}, {%0,%1,%2,%3};\n"
        : "+f"(c[0]), "+f"(c[1]), "+f"(c[2]), "+f"(c[3])
        : "r"(a[0]), "r"(a[1]), "r"(a[2]), "r"(a[3]), "r"(b0), "r"(b1));
}

__device__ __forceinline__ void ldsm_x4(uint32_t r[4], uint32_t addr) {
    asm volatile("ldmatrix.sync.aligned.m8n8.x4.shared.b16 {%0,%1,%2,%3}, [%4];"
                 : "=r"(r[0]), "=r"(r[1]), "=r"(r[2]), "=r"(r[3]) : "r"(addr));
}
__device__ __forceinline__ void ldsm_x4_t(uint32_t r[4], uint32_t addr) {
    asm volatile("ldmatrix.sync.aligned.m8n8.x4.trans.shared.b16 {%0,%1,%2,%3}, [%4];"
                 : "=r"(r[0]), "=r"(r[1]), "=r"(r[2]), "=r"(r[3]) : "r"(addr));
}

// cp.async one 64x64-bf16 tile (64 rows x 128B) into swizzled smem
__device__ __forceinline__ void load_tile_async(uint32_t dst,
                                                const __nv_bfloat16* src, int t) {
#pragma unroll
    for (int e = t; e < 512; e += 128) {
        int row = e >> 3, chunk = e & 7;
        uint32_t d = dst + row * 128 + ((chunk ^ (row & 7)) << 4);
        const void* s = (const uint8_t*)(src + (size_t)row * NCI) + chunk * 16;
        asm volatile("cp.async.cg.shared.global [%0], [%1], 16;\n" :: "r"(d), "l"(s));
    }
}

// ---------------------------------------------------------------------------
// Projections: out[n][ci] = sum_c w[ci][c] * x[c][n] + b[ci]   (bf16 output)
// z=0: theta(x1); z=1: phi(x0); z=2: g(x0).
// ---------------------------------------------------------------------------
__global__ void __launch_bounds__(256) proj_kernel(
    const float* __restrict__ x0, const float* __restrict__ x1,
    const float* __restrict__ theta_w, const float* __restrict__ theta_b,
    const float* __restrict__ phi_w,   const float* __restrict__ phi_b,
    const float* __restrict__ g_w,     const float* __restrict__ g_b)
{
    __shared__ __align__(16) float ws[64 * 64];   // [c_local][ci]
    __shared__ __align__(16) float xs[64 * 128];  // [c_local][p]

    int b = blockIdx.y;
    int n0 = blockIdx.x * 128;
    int which = blockIdx.z;
    const float* w    = (which == 0) ? theta_w : ((which == 1) ? phi_w : g_w);
    const float* bias = (which == 0) ? theta_b : ((which == 1) ? phi_b : g_b);
    const float* src  = (which == 0) ? x1 : x0;

    int t = threadIdx.x;
    int tx = t & 15, ty = t >> 4;
    int ci0 = ty * 4, p0 = tx * 4;

    float acc[4][8];
#pragma unroll
    for (int i = 0; i < 4; i++)
#pragma unroll
        for (int j = 0; j < 8; j++) acc[i][j] = 0.0f;

    const float* xb = src + (size_t)b * NC * NN + n0;

    for (int h = 0; h < 2; h++) {
        if (h) __syncthreads();
        for (int e = t; e < 64 * 64; e += 256) {
            int ci = e >> 6, cl = e & 63;
            ws[cl * 64 + ci] = w[ci * NC + h * 64 + cl];
        }
        for (int e = t; e < 64 * 128; e += 256) {
            int cl = e >> 7, p = e & 127;
            xs[cl * 128 + p] = xb[(size_t)(h * 64 + cl) * NN + p];
        }
        __syncthreads();
#pragma unroll 4
        for (int cl = 0; cl < 64; cl++) {
            float4 wv = *(const float4*)&ws[cl * 64 + ci0];
            float4 xa = *(const float4*)&xs[cl * 128 + p0];
            float4 xc = *(const float4*)&xs[cl * 128 + p0 + 64];
            float wr[4] = {wv.x, wv.y, wv.z, wv.w};
            float xr[8] = {xa.x, xa.y, xa.z, xa.w, xc.x, xc.y, xc.z, xc.w};
#pragma unroll
            for (int i = 0; i < 4; i++)
#pragma unroll
                for (int j = 0; j < 8; j++)
                    acc[i][j] = fmaf(wr[i], xr[j], acc[i][j]);
        }
    }

    __nv_bfloat16* out = ((which == 0) ? d_theta : ((which == 1) ? d_phi : d_g))
                         + (size_t)b * NN * NCI + (size_t)n0 * NCI;
    float b0v = bias[ci0], b1v = bias[ci0 + 1], b2v = bias[ci0 + 2], b3v = bias[ci0 + 3];
#pragma unroll
    for (int jj = 0; jj < 8; jj++) {
        int p = (jj < 4) ? (p0 + jj) : (p0 + 60 + jj);
        uint2 v;
        v.x = pack_bf16(acc[0][jj] + b0v, acc[1][jj] + b1v);
        v.y = pack_bf16(acc[2][jj] + b2v, acc[3][jj] + b3v);
        *(uint2*)&out[(size_t)p * NCI + ci0] = v;
    }
}

// ---------------------------------------------------------------------------
// Flash attention, bf16 m16n8k16 mma. One CTA = 64 queries, 4 warps, 128 thr.
// Q a-frags register-resident (via ldmatrix from staged smem).
// K tile [kidx][d], V tile [kidx][d] in smem, 128B rows, chunk^(row&7) swizzle.
// S B-frags: ldmatrix.x4; V B-frags: ldmatrix.x4.trans.
// P A-frags = packed S C-frags (no shuffles). cp.async double buffering.
// ---------------------------------------------------------------------------
__global__ void __launch_bounds__(128) attn_kernel()
{
    __shared__ __align__(16) uint8_t Qsm[64 * 128];
    __shared__ __align__(16) uint8_t Ksm[2][64 * 128];
    __shared__ __align__(16) uint8_t Vsm[2][64 * 128];

    int b = blockIdx.y;
    int qb = blockIdx.x * 64;
    int t = threadIdx.x;
    int w = t >> 5, lane = t & 31;
    int g = lane >> 2, j = lane & 3;
    int sel = lane >> 3, l7 = lane & 7;

    const __nv_bfloat16* Qg = d_theta + (size_t)b * NN * NCI + (size_t)qb * NCI;
    const __nv_bfloat16* Kg = d_phi   + (size_t)b * NN * NCI;
    const __nv_bfloat16* Vg = d_g     + (size_t)b * NN * NCI;

    uint32_t smQ  = smem_u32(Qsm);
    uint32_t smK0 = smem_u32(Ksm[0]), smK1 = smem_u32(Ksm[1]);
    uint32_t smV0 = smem_u32(Vsm[0]), smV1 = smem_u32(Vsm[1]);

    // prologue: start tile-0 K/V loads
    load_tile_async(smK0, Kg, t);
    load_tile_async(smV0, Vg, t);
    asm volatile("cp.async.commit_group;\n");

    // stage Q tile (overlaps with the cp.async above)
#pragma unroll
    for (int e = t; e < 512; e += 128) {
        int row = e >> 3, chunk = e & 7;
        uint4 v = *(const uint4*)((const uint8_t*)(Qg + (size_t)row * NCI) + chunk * 16);
        *(uint4*)&Qsm[row * 128 + ((chunk ^ (row & 7)) << 4)] = v;
    }
    __syncthreads();

    // Q a-frags for 4 k-steps (d = 16*ks .. 16*ks+15)
    uint32_t qa[4][4];
#pragma unroll
    for (int ks = 0; ks < 4; ks++) {
        int row = w * 16 + ((sel & 1) << 3) + l7;
        int chunk = 2 * ks + (sel >> 1);
        ldsm_x4(qa[ks], smQ + row * 128 + ((chunk ^ (row & 7)) << 4));
    }

    float o[8][4];
#pragma unroll
    for (int nt = 0; nt < 8; nt++)
#pragma unroll
        for (int i = 0; i < 4; i++) o[nt][i] = 0.0f;
    float m0 = -1e30f, m1 = -1e30f, l0 = 0.0f, l1 = 0.0f;

    for (int it = 0; it < NN / 64; it++) {
        uint32_t smKb = (it & 1) ? smK1 : smK0;
        uint32_t smVb = (it & 1) ? smV1 : smV0;
        if (it + 1 < NN / 64) {
            uint32_t smKn = (it & 1) ? smK0 : smK1;
            uint32_t smVn = (it & 1) ? smV0 : smV1;
            load_tile_async(smKn, Kg + (size_t)(it + 1) * 64 * NCI, t);
            load_tile_async(smVn, Vg + (size_t)(it + 1) * 64 * NCI, t);
            asm volatile("cp.async.commit_group;\n");
            asm volatile("cp.async.wait_group 1;\n");
        } else {
            asm volatile("cp.async.wait_group 0;\n");
        }
        __syncthreads();

        // ---- S = Q K^T ----
        float s[8][4];
#pragma unroll
        for (int nt = 0; nt < 8; nt++)
#pragma unroll
            for (int i = 0; i < 4; i++) s[nt][i] = 0.0f;

#pragma unroll
        for (int ks = 0; ks < 4; ks++) {
#pragma unroll
            for (int ntp = 0; ntp < 4; ntp++) {
                int row = ntp * 16 + ((sel >> 1) << 3) + l7;
                int chunk = 2 * ks + (sel & 1);
                uint32_t r[4];
                ldsm_x4(r, smKb + row * 128 + ((chunk ^ (row & 7)) << 4));
                mma_bf16(s[2 * ntp], qa[ks], r[0], r[1]);
                mma_bf16(s[2 * ntp + 1], qa[ks], r[2], r[3]);
            }
        }

        // ---- online softmax: rows g (regs 0,1) and g+8 (regs 2,3) ----
        float t0 = -1e30f, t1 = -1e30f;
#pragma unroll
        for (int nt = 0; nt < 8; nt++) {
            t0 = fmaxf(t0, fmaxf(s[nt][0], s[nt][1]));
            t1 = fmaxf(t1, fmaxf(s[nt][2], s[nt][3]));
        }
        t0 = fmaxf(t0, __shfl_xor_sync(0xffffffffu, t0, 1));
        t0 = fmaxf(t0, __shfl_xor_sync(0xffffffffu, t0, 2));
        t1 = fmaxf(t1, __shfl_xor_sync(0xffffffffu, t1, 1));
        t1 = fmaxf(t1, __shfl_xor_sync(0xffffffffu, t1, 2));
        float nm0 = fmaxf(m0, t0), nm1 = fmaxf(m1, t1);
        float sc0 = fast_exp(m0 - nm0), sc1 = fast_exp(m1 - nm1);
        float rs0 = 0.0f, rs1 = 0.0f;
#pragma unroll
        for (int nt = 0; nt < 8; nt++) {
            s[nt][0] = fast_exp(s[nt][0] - nm0);
            s[nt][1] = fast_exp(s[nt][1] - nm0);
            s[nt][2] = fast_exp(s[nt][2] - nm1);
            s[nt][3] = fast_exp(s[nt][3] - nm1);
            rs0 += s[nt][0] + s[nt][1];
            rs1 += s[nt][2] + s[nt][3];
        }
        rs0 += __shfl_xor_sync(0xffffffffu, rs0, 1);
        rs0 += __shfl_xor_sync(0xffffffffu, rs0, 2);
        rs1 += __shfl_xor_sync(0xffffffffu, rs1, 1);
        rs1 += __shfl_xor_sync(0xffffffffu, rs1, 2);
        l0 = fmaf(l0, sc0, rs0);
        l1 = fmaf(l1, sc1, rs1);
        m0 = nm0; m1 = nm1;
#pragma unroll
        for (int nt = 0; nt < 8; nt++) {
            o[nt][0] *= sc0; o[nt][1] *= sc0;
            o[nt][2] *= sc1; o[nt][3] *= sc1;
        }

        // ---- O += P V : P A-frags = packed C-frags ----
#pragma unroll
        for (int ks = 0; ks < 4; ks++) {
            uint32_t ap[4];
            ap[0] = pack_bf16(s[2 * ks][0], s[2 * ks][1]);
            ap[1] = pack_bf16(s[2 * ks][2], s[2 * ks][3]);
            ap[2] = pack_bf16(s[2 * ks + 1][0], s[2 * ks + 1][1]);
            ap[3] = pack_bf16(s[2 * ks + 1][2], s[2 * ks + 1][3]);
#pragma unroll
            for (int ntp = 0; ntp < 4; ntp++) {
                int row = 16 * ks + ((sel & 1) << 3) + l7;
                int chunk = 2 * ntp + (sel >> 1);
                uint32_t r[4];
                ldsm_x4_t(r, smVb + row * 128 + ((chunk ^ (row & 7)) << 4));
                mma_bf16(o[2 * ntp], ap, r[0], r[1]);
                mma_bf16(o[2 * ntp + 1], ap, r[2], r[3]);
            }
        }
        __syncthreads();
    }

    // ---- epilogue: y[b][d][n] = O / l   (fp32, [ci][n]) ----
    float inv0 = 1.0f / l0, inv1 = 1.0f / l1;
    float* yo = d_y + (size_t)b * NCI * NN;
    int q0 = qb + w * 16;
    int qg0 = q0 + g, qg1 = q0 + g + 8;
#pragma unroll
    for (int nt = 0; nt < 8; nt++) {
        int d0 = nt * 8 + 2 * j;
        yo[(size_t)d0 * NN + qg0]       = o[nt][0] * inv0;
        yo[(size_t)(d0 + 1) * NN + qg0] = o[nt][1] * inv0;
        yo[(size_t)d0 * NN + qg1]       = o[nt][2] * inv1;
        yo[(size_t)(d0 + 1) * NN + qg1] = o[nt][3] * inv1;
    }
}

// ---------------------------------------------------------------------------
// out[b][co][n] = sum_ci Ww[co][ci] * y[b][ci][n] + Wb[co] + x0[b][co][n]
// ---------------------------------------------------------------------------
__global__ void __launch_bounds__(256) out_kernel(
    const float* __restrict__ x0, const float* __restrict__ Ww,
    const float* __restrict__ Wb, float* __restrict__ out)
{
    __shared__ __align__(16) float ws[32 * 128]; // [ci_local][co]
    __shared__ __align__(16) float ys[32 * 128]; // [ci_local][p]

    int b = blockIdx.y;
    int n0 = blockIdx.x * 128;
    int t = threadIdx.x;
    int tx = t & 15, ty = t >> 4;
    int co0 = ty * 4, p0 = tx * 4;

    float acc[8][8];
#pragma unroll
    for (int i = 0; i < 8; i++)
#pragma unroll
        for (int j = 0; j < 8; j++) acc[i][j] = 0.0f;

    const float* yg = d_y + (size_t)b * NCI * NN + n0;

    for (int h = 0; h < 2; h++) {
        if (h) __syncthreads();
        for (int e = t; e < 128 * 32; e += 256) {
            int co = e >> 5, cil = e & 31;
            ws[cil * 128 + co] = Ww[co * NCI + h * 32 + cil];
        }
        for (int e = t; e < 32 * 128; e += 256) {
            int cil = e >> 7, p = e & 127;
            ys[cil * 128 + p] = yg[(size_t)(h * 32 + cil) * NN + p];
        }
        __syncthreads();
#pragma unroll 4
        for (int cil = 0; cil < 32; cil++) {
            float4 wa = *(const float4*)&ws[cil * 128 + co0];
            float4 wc = *(const float4*)&ws[cil * 128 + co0 + 64];
            float4 ya = *(const float4*)&ys[cil * 128 + p0];
            float4 yc = *(const float4*)&ys[cil * 128 + p0 + 64];
            float wr[8] = {wa.x, wa.y, wa.z, wa.w, wc.x, wc.y, wc.z, wc.w};
            float yr[8] = {ya.x, ya.y, ya.z, ya.w, yc.x, yc.y, yc.z, yc.w};
#pragma unroll
            for (int i = 0; i < 8; i++)
#pragma unroll
                for (int j = 0; j < 8; j++)
                    acc[i][j] = fmaf(wr[i], yr[j], acc[i][j]);
        }
    }

    const float* xb = x0 + (size_t)b * NC * NN + n0;
    float* ob = out + (size_t)b * NC * NN + n0;
#pragma unroll
    for (int ih = 0; ih < 2; ih++)
#pragma unroll
        for (int i = 0; i < 4; i++) {
            int co = co0 + ih * 64 + i;
            float bv = Wb[co];
            int ai = ih * 4 + i;
#pragma unroll
            for (int jh = 0; jh < 2; jh++) {
                int p = p0 + jh * 64;
                int aj = jh * 4;
                float4 xv = *(const float4*)&xb[(size_t)co * NN + p];
                float4 r = make_float4(acc[ai][aj + 0] + bv + xv.x,
                                       acc[ai][aj + 1] + bv + xv.y,
                                       acc[ai][aj + 2] + bv + xv.z,
                                       acc[ai][aj + 3] + bv + xv.w);
                *(float4*)&ob[(size_t)co * NN + p] = r;
            }
        }
}

extern "C" void kernel_launch(void* const* d_in, const int* in_sizes, int n_in,
                              void* d_out, int out_size)
{
    const float* x0   = (const float*)d_in[0];
    const float* x1   = (const float*)d_in[1];
    const float* g_w  = (const float*)d_in[2];
    const float* g_b  = (const float*)d_in[3];
    const float* th_w = (const float*)d_in[4];
    const float* th_b = (const float*)d_in[5];
    const float* ph_w = (const float*)d_in[6];
    const float* ph_b = (const float*)d_in[7];
    const float* W_w  = (const float*)d_in[8];
    const float* W_b  = (const float*)d_in[9];
    float* out = (float*)d_out;

    proj_kernel<<<dim3(NN / 128, NB, 3), 256>>>(x0, x1, th_w, th_b, ph_w, ph_b, g_w, g_b);
    attn_kernel<<<dim3(NN / 64, NB), 128>>>();
    out_kernel<<<dim3(NN / 128, NB), 256>>>(x0, W_w, W_b, out);
}